// round 10
// baseline (speedup 1.0000x reference)
#include <cuda_runtime.h>
#include <cuda_bf16.h>
#include <math.h>
#include <stdint.h>

#define BB 2
#define SS 2048
#define DD 1024
#define HH 16
#define HD 64
#define BH (BB*HH)
#define NKEEP 675
#define W2 64
#define SA 40   // smem row stride (bf16), 32-wide K chunks
#define SA2 72  // smem row stride (bf16), 64-wide K chunks

// ---------------- scratch -----------------------------------------------------
__device__ float g_sq[BH*SS];
__device__ float g_d2c[BH*SS];
__device__ float g_d2cmax[BH];
__device__ float g_kd[BH*SS];
__device__ float g_kdmax[BH];
__device__ float g_tls[BH*SS];
__device__ int   g_mark[BH*SS];

__device__ __align__(256) __nv_bfloat16 g_xhi[BB*SS*DD];
__device__ __align__(256) __nv_bfloat16 g_xlo[BB*SS*DD];
__device__ __align__(256) __nv_bfloat16 g_w3hi[3*DD*DD];
__device__ __align__(256) __nv_bfloat16 g_w3lo[3*DD*DD];
__device__ __align__(256) __nv_bfloat16 g_w1hi[DD*DD];
__device__ __align__(256) __nv_bfloat16 g_w1lo[DD*DD];
__device__ __align__(256) __nv_bfloat16 g_qhi[BH*SS*HD];
__device__ __align__(256) __nv_bfloat16 g_qlo[BH*SS*HD];
__device__ __align__(256) __nv_bfloat16 g_khi[BH*SS*HD];
__device__ __align__(256) __nv_bfloat16 g_klo[BH*SS*HD];
__device__ __align__(256) __nv_bfloat16 g_vthi[BH*HD*SS];  // V^T: [bh][d][s]
__device__ __align__(256) __nv_bfloat16 g_vtlo[BH*HD*SS];
__device__ __align__(256) __nv_bfloat16 g_ohi[BB*SS*DD];
__device__ __align__(256) __nv_bfloat16 g_olo[BB*SS*DD];

// ---------------- helpers -----------------------------------------------------
__device__ __forceinline__ uint32_t s2u(const void* p) {
    uint32_t a;
    asm("{ .reg .u64 t; cvta.to.shared.u64 t, %1; cvt.u32.u64 %0, t; }" : "=r"(a) : "l"(p));
    return a;
}
__device__ __forceinline__ void mma16816(float* c, const uint32_t* a, const uint32_t* b) {
    asm volatile(
        "mma.sync.aligned.m16n8k16.row.col.f32.bf16.bf16.f32 "
        "{%0,%1,%2,%3}, {%4,%5,%6,%7}, {%8,%9}, {%0,%1,%2,%3};"
        : "+f"(c[0]), "+f"(c[1]), "+f"(c[2]), "+f"(c[3])
        : "r"(a[0]), "r"(a[1]), "r"(a[2]), "r"(a[3]), "r"(b[0]), "r"(b[1]));
}
__device__ __forceinline__ void ldsm_x4(uint32_t* r, uint32_t addr) {
    asm volatile("ldmatrix.sync.aligned.m8n8.x4.shared.b16 {%0,%1,%2,%3}, [%4];"
                 : "=r"(r[0]), "=r"(r[1]), "=r"(r[2]), "=r"(r[3]) : "r"(addr));
}
__device__ __forceinline__ void split2(float x, float y, uint32_t& hi, uint32_t& lo) {
    __nv_bfloat16 hx = __float2bfloat16(x), hy = __float2bfloat16(y);
    __nv_bfloat162 h, l;
    h.x = hx; h.y = hy;
    l.x = __float2bfloat16(x - __bfloat162float(hx));
    l.y = __float2bfloat16(y - __bfloat162float(hy));
    hi = *(uint32_t*)&h;
    lo = *(uint32_t*)&l;
}
__device__ __forceinline__ void cp8(__nv_bfloat16* dst, const __nv_bfloat16* src) {
    uint32_t d = s2u(dst);
    asm volatile("cp.async.ca.shared.global [%0], [%1], 8;" :: "r"(d), "l"(src) : "memory");
}
#define CP_COMMIT() asm volatile("cp.async.commit_group;" ::: "memory")
#define CP_WAIT1() asm volatile("cp.async.wait_group 1;" ::: "memory")
#define CP_WAIT0() asm volatile("cp.async.wait_group 0;" ::: "memory")

// cp.async stage of a [128 x 32] bf16 tile -> smem [128][SA]
__device__ __forceinline__ void stage_cp(__nv_bfloat16* dst, const __nv_bfloat16* src,
                                         int ld, int k0, int t) {
#pragma unroll
    for (int i = 0; i < 4; i++) {
        int lin = t + i * 256;
        int r = lin >> 3, h = lin & 7;
        cp8(&dst[r * SA + h * 4], &src[(size_t)r * ld + k0 + h * 4]);
    }
}
// cp.async stage of a [128 x 64] bf16 tile -> smem [128][SA2]
__device__ __forceinline__ void stage_cp64(__nv_bfloat16* dst, const __nv_bfloat16* src,
                                           int ld, int t) {
#pragma unroll
    for (int i = 0; i < 8; i++) {
        int lin = t + i * 256;
        int r = lin >> 4, h = lin & 15;
        cp8(&dst[r * SA2 + h * 4], &src[(size_t)r * ld + h * 4]);
    }
}

// ---- fused-pass MMA over one K chunk via ldmatrix, pass-outer issue order ----
// p0 = Ah*Bh, p1 = Ah*Bl, p2 = Al*Bh, p3 = Al*Bl (per-acc order unchanged)
template<int STR, int NSTEP, int NPASS>
__device__ __forceinline__ void mma_chunk(uint32_t Ah, uint32_t Al,
                                          uint32_t Bh, uint32_t Bl,
                                          int wm, int wn, int lane, float (*acc)[4][4]) {
    int quad = lane >> 3, within = lane & 7;
    int arow = (wm + within + (quad & 1) * 8) * STR + (quad >> 1) * 8;
    int brow = (wn + within + (quad >> 1) * 8) * STR + (quad & 1) * 8;
#pragma unroll
    for (int s = 0; s < NSTEP; s++) {
        int kk = s * 16;
        uint32_t ah[4][4], al[4][4], bh[2][4], bl[2][4];
#pragma unroll
        for (int mt = 0; mt < 4; mt++) {
            uint32_t off = (uint32_t)(arow + mt * 16 * STR + kk) * 2;
            ldsm_x4(ah[mt], Ah + off);
            ldsm_x4(al[mt], Al + off);
        }
#pragma unroll
        for (int np = 0; np < 2; np++) {
            uint32_t off = (uint32_t)(brow + np * 16 * STR + kk) * 2;
            ldsm_x4(bh[np], Bh + off);
            ldsm_x4(bl[np], Bl + off);
        }
#pragma unroll
        for (int p = 0; p < NPASS; p++) {
            const uint32_t (*ap)[4] = (p >= 2) ? al : ah;
#pragma unroll
            for (int nt = 0; nt < 4; nt++) {
                const uint32_t* bp = (p & 1) ? &bl[nt >> 1][(nt & 1) * 2]
                                             : &bh[nt >> 1][(nt & 1) * 2];
#pragma unroll
                for (int mt = 0; mt < 4; mt++)
                    mma16816(acc[mt][nt], ap[mt], bp);
            }
        }
    }
}

// double-buffered mainloop for K>=128 GEMMs (tiles: 0=Ahi 1=Alo 2=Bhi 3=Blo)
#define TILE_BYTES (128 * SA * 2)
__device__ __forceinline__ void gemm_db(const __nv_bfloat16* Ahi, const __nv_bfloat16* Alo, int lda,
                                        const __nv_bfloat16* Bhi, const __nv_bfloat16* Blo, int ldb,
                                        int K, char* dsm, int t, int wm, int wn,
                                        int lane, float (*acc)[4][4]) {
    uint32_t base = s2u(dsm);
    auto tile = [&](int buf, int idx) {
        return (__nv_bfloat16*)(dsm + (buf * 4 + idx) * TILE_BYTES);
    };
    stage_cp(tile(0, 0), Ahi, lda, 0, t);
    stage_cp(tile(0, 1), Alo, lda, 0, t);
    stage_cp(tile(0, 2), Bhi, ldb, 0, t);
    stage_cp(tile(0, 3), Blo, ldb, 0, t);
    CP_COMMIT();
    int nch = K / 32;
    for (int ch = 0; ch < nch; ++ch) {
        int buf = ch & 1;
        if (ch + 1 < nch) {
            int nb = buf ^ 1, k0 = (ch + 1) * 32;
            stage_cp(tile(nb, 0), Ahi, lda, k0, t);
            stage_cp(tile(nb, 1), Alo, lda, k0, t);
            stage_cp(tile(nb, 2), Bhi, ldb, k0, t);
            stage_cp(tile(nb, 3), Blo, ldb, k0, t);
            CP_COMMIT();
            CP_WAIT1();
        } else {
            CP_WAIT0();
        }
        __syncthreads();
        uint32_t tb = base + buf * 4 * TILE_BYTES;
        mma_chunk<SA, 2, 3>(tb, tb + TILE_BYTES, tb + 2 * TILE_BYTES, tb + 3 * TILE_BYTES,
                            wm, wn, lane, acc);
        __syncthreads();
    }
}
#define GEMM_DSMEM (8 * TILE_BYTES)

#define GEMM_PROLOG() \
    extern __shared__ char dsm[]; \
    int t = threadIdx.x, w = t >> 5, lane = t & 31; \
    int wm = (w & 1) * 64, wn = (w >> 1) * 32; \
    int g = lane >> 2, tg = lane & 3; \
    float acc[4][4][4] = {};

// ---------------- cvt: fp32 -> (hi, lo) bf16 ----------------------------------
__global__ __launch_bounds__(256) void cvt_x(const float* __restrict__ s) {
    int i = blockIdx.x * 256 + threadIdx.x;
    if (i < BB * SS * DD) {
        float v = s[i];
        __nv_bfloat16 h = __float2bfloat16(v);
        g_xhi[i] = h;
        g_xlo[i] = __float2bfloat16(v - __bfloat162float(h));
    }
}
__global__ __launch_bounds__(256) void cvt_w3(const float* __restrict__ s) {
    int i = blockIdx.x * 256 + threadIdx.x;
    if (i < 3 * DD * DD) {
        float v = s[i];
        __nv_bfloat16 h = __float2bfloat16(v);
        g_w3hi[i] = h;
        g_w3lo[i] = __float2bfloat16(v - __bfloat162float(h));
    }
}
__global__ __launch_bounds__(256) void cvt_w1(const float* __restrict__ s) {
    int i = blockIdx.x * 256 + threadIdx.x;
    if (i < DD * DD) {
        float v = s[i];
        __nv_bfloat16 h = __float2bfloat16(v);
        g_w1hi[i] = h;
        g_w1lo[i] = __float2bfloat16(v - __bfloat162float(h));
    }
}

// ---------------- K1: QKV GEMM ------------------------------------------------
__global__ __launch_bounds__(256, 2) void qkv_mma(const float* __restrict__ bias) {
    GEMM_PROLOG();
    int bx = blockIdx.x, by = blockIdx.y;
    gemm_db(g_xhi + (size_t)by * 128 * DD, g_xlo + (size_t)by * 128 * DD, DD,
            g_w3hi + (size_t)bx * 128 * DD, g_w3lo + (size_t)bx * 128 * DD, DD,
            DD, dsm, t, wm, wn, lane, acc);
#pragma unroll
    for (int mt = 0; mt < 4; mt++)
#pragma unroll
        for (int nt = 0; nt < 4; nt++) {
            float* c = acc[mt][nt];
#pragma unroll
            for (int half = 0; half < 2; half++) {
                int m = by * 128 + wm + mt * 16 + g + half * 8;
                int n = bx * 128 + wn + nt * 8 + tg * 2;
                float v0 = c[half * 2] + bias[n];
                float v1 = c[half * 2 + 1] + bias[n + 1];
                int which = n >> 10, h = (n >> 6) & 15, d = n & 63;
                int b = m >> 11, s = m & (SS - 1);
                int bh = b * HH + h;
                if (which == 0) {
                    size_t di = ((size_t)bh * SS + s) * HD + d;
                    uint32_t hi, lo;
                    split2(v0 * 0.125f, v1 * 0.125f, hi, lo);
                    *(uint32_t*)&g_qhi[di] = hi;
                    *(uint32_t*)&g_qlo[di] = lo;
                } else if (which == 1) {
                    size_t di = ((size_t)bh * SS + s) * HD + d;
                    uint32_t hi, lo;
                    split2(v0, v1, hi, lo);
                    *(uint32_t*)&g_khi[di] = hi;
                    *(uint32_t*)&g_klo[di] = lo;
                } else {
                    size_t di = ((size_t)bh * HD + d) * SS + s;
                    __nv_bfloat16 h0 = __float2bfloat16(v0), h1 = __float2bfloat16(v1);
                    g_vthi[di] = h0;
                    g_vtlo[di] = __float2bfloat16(v0 - __bfloat162float(h0));
                    g_vthi[di + SS] = h1;
                    g_vtlo[di + SS] = __float2bfloat16(v1 - __bfloat162float(h1));
                }
            }
        }
}

// ---------------- K2: stats ---------------------------------------------------
__global__ __launch_bounds__(256) void stats_kernel(const float* __restrict__ x) {
    int bh = blockIdx.x;
    int b = bh / HH, h = bh % HH;
    int t = threadIdx.x;
    __shared__ float part[256];
    __shared__ float cent[64];
    int d = t & 63, grp = t >> 6;
    float acc = 0.f;
    for (int s = grp; s < SS; s += 4)
        acc += x[((size_t)(b * SS + s)) * DD + h * HD + d];
    part[t] = acc;
    __syncthreads();
    if (t < 64) cent[t] = (part[t] + part[t + 64] + part[t + 128] + part[t + 192]) * (1.0f / SS);
    __syncthreads();
    float lmax = 0.f;
    for (int s = t; s < SS; s += 256) {
        const float* xp = x + (size_t)(b * SS + s) * DD + h * HD;
        float sq = 0.f, dc2 = 0.f;
#pragma unroll
        for (int dd = 0; dd < HD; ++dd) {
            float v = xp[dd];
            sq += v * v;
            float wv = v - cent[dd];
            dc2 += wv * wv;
        }
        g_sq[bh * SS + s] = sq;
        float dc = sqrtf(dc2);
        g_d2c[bh * SS + s] = dc;
        lmax = fmaxf(lmax, dc);
    }
    __syncthreads();
    part[t] = lmax;
    __syncthreads();
    for (int off = 128; off > 0; off >>= 1) {
        if (t < off) part[t] = fmaxf(part[t], part[t + off]);
        __syncthreads();
    }
    if (t == 0) {
        g_d2cmax[bh] = part[0];
        g_kdmax[bh] = 0.f;
    }
}

// ---------------- K3+K4 fused: pairwise dist + 10th-smallest (occ 2) ----------
#define T64 (128 * SA2 * 2)
#define DK_SD (4 * T64)
#define DIST_SMEM (DK_SD + 128 * 66 * 4)
__global__ __launch_bounds__(256, 2) void distkth_mma() {
    extern __shared__ char dsm[];
    uint32_t base = s2u(dsm);
    __nv_bfloat16* aH = (__nv_bfloat16*)dsm;
    __nv_bfloat16* aL = (__nv_bfloat16*)(dsm + T64);
    __nv_bfloat16* bH = (__nv_bfloat16*)(dsm + 2 * T64);
    __nv_bfloat16* bL = (__nv_bfloat16*)(dsm + 3 * T64);
    float* sD = (float*)(dsm + DK_SD);
    int t = threadIdx.x, w = t >> 5, lane = t & 31;
    int wm = (w & 1) * 64, wn = (w >> 1) * 32;
    int g = lane >> 2, tg = lane & 3;
    int wphase = w >> 2;
    int bh = blockIdx.y;
    int m0 = blockIdx.x * 128;
    const __nv_bfloat16* xh = g_xhi + (size_t)(bh >> 4) * SS * DD + (bh & 15) * HD;
    const __nv_bfloat16* xl = g_xlo + (size_t)(bh >> 4) * SS * DD + (bh & 15) * HD;

#pragma unroll
    for (int i = 0; i < 8; i++) {
        int lin = t + i * 256;
        int r = lin >> 4, hh = lin & 15;
        *(uint2*)&aH[r * SA2 + hh * 4] = *(const uint2*)&xh[(size_t)(m0 + r) * DD + hh * 4];
        *(uint2*)&aL[r * SA2 + hh * 4] = *(const uint2*)&xl[(size_t)(m0 + r) * DD + hh * 4];
    }

    float ls[10];
#pragma unroll
    for (int q = 0; q < 10; q++) ls[q] = 1e30f;
    int row_l = t >> 1;
    int hhalf = t & 1;

    for (int ct = 0; ct < 16; ++ct) {
        stage_cp64(bH, xh + (size_t)ct * 128 * DD, DD, t);
        stage_cp64(bL, xl + (size_t)ct * 128 * DD, DD, t);
        CP_COMMIT();
        CP_WAIT0();
        __syncthreads();
        float acc[4][4][4];
#pragma unroll
        for (int a = 0; a < 4; a++)
#pragma unroll
            for (int b2 = 0; b2 < 4; b2++)
#pragma unroll
                for (int c2 = 0; c2 < 4; c2++) acc[a][b2][c2] = 0.f;
        mma_chunk<SA2, 4, 4>(base, base + T64, base + 2 * T64, base + 3 * T64,
                             wm, wn, lane, acc);
#pragma unroll
        for (int p = 0; p < 2; p++) {
            if (wphase == p) {
#pragma unroll
                for (int mt = 0; mt < 4; mt++)
#pragma unroll
                    for (int nt = 0; nt < 4; nt++) {
                        float* c = acc[mt][nt];
#pragma unroll
                        for (int half = 0; half < 2; half++) {
                            int ml = wm + mt * 16 + g + half * 8;
                            int nl = wn + nt * 8 + tg * 2;
                            float2 sqj = *(const float2*)&g_sq[bh * SS + ct * 128 + nl];
                            sD[ml * 66 + (nl - p * 64)] = sqj.x - 2.f * c[half * 2];
                            sD[ml * 66 + (nl - p * 64) + 1] = sqj.y - 2.f * c[half * 2 + 1];
                        }
                    }
            }
            __syncthreads();
            const float* rp = &sD[row_l * 66 + hhalf * 32];
#pragma unroll 8
            for (int i = 0; i < 32; ++i) {
                float v = rp[i];
                if (v < ls[9]) {
                    ls[9] = v;
#pragma unroll
                    for (int q = 9; q > 0; --q) {
                        if (ls[q] < ls[q - 1]) { float tm = ls[q]; ls[q] = ls[q - 1]; ls[q - 1] = tm; }
                    }
                }
            }
            __syncthreads();
        }
    }
#pragma unroll
    for (int q = 0; q < 10; q++) sD[row_l * 66 + hhalf * 10 + q] = ls[q];
    __syncthreads();
    if (hhalf == 0) {
        const float* a = &sD[row_l * 66];
        const float* b = a + 10;
        int ia = 0, ib = 0;
        float kth = 0.f;
#pragma unroll
        for (int it = 0; it < 10; ++it)
            kth = (a[ia] <= b[ib]) ? a[ia++] : b[ib++];
        int m = m0 + row_l;
        float kd = sqrtf(fmaxf(g_sq[bh * SS + m] + kth, 0.f));
        g_kd[bh * SS + m] = kd;
        atomicMax((int*)&g_kdmax[bh], __float_as_int(kd));
    }
}

// ---------------- K5: tls -----------------------------------------------------
__global__ __launch_bounds__(256) void tls_kernel() {
    int bh = blockIdx.x;
    int t = threadIdx.x;
    float dinv = 1.0f / (g_d2cmax[bh] + 1e-8f);
    float kinv = 1.0f / (g_kdmax[bh] + 1e-8f);
    for (int s = t; s < SS; s += 256) {
        float life = g_d2c[bh * SS + s] * dinv;
        float mmd = g_kd[bh * SS + s] * kinv;
        g_tls[bh * SS + s] = 0.7f * life + 0.3f * mmd;
    }
}

// ---------------- K6: bitonic sort + mark -------------------------------------
__global__ __launch_bounds__(1024) void sort_mark_kernel() {
    __shared__ float a[SS];
    int t = threadIdx.x;
    int bh = blockIdx.x;
    a[t] = g_tls[bh * SS + t];
    a[t + 1024] = g_tls[bh * SS + t + 1024];
    __syncthreads();
    for (int k = 2; k <= SS; k <<= 1) {
        for (int j = k >> 1; j > 0; j >>= 1) {
#pragma unroll
            for (int half = 0; half < 2; ++half) {
                int i = t + half * 1024;
                int ixj = i ^ j;
                if (ixj > i) {
                    bool up = ((i & k) == 0);
                    float xi = a[i], xj = a[ixj];
                    if (up ? (xi > xj) : (xi < xj)) { a[i] = xj; a[ixj] = xi; }
                }
            }
            __syncthreads();
        }
    }
    float thresh = a[SS - NKEEP];
    __syncthreads();
#pragma unroll
    for (int half = 0; half < 2; ++half) {
        int s = t + half * 1024;
        g_mark[bh * SS + s] = (g_tls[bh * SS + s] >= thresh) ? 1 : 0;
    }
}

// ---------------- K7: score GEMM (single 64-wide chunk, occ 2) ----------------
#define SCORE_SMEM (4 * T64)
__global__ __launch_bounds__(256, 2) void score_mma(float* __restrict__ attn) {
    extern __shared__ char dsm[];
    uint32_t base = s2u(dsm);
    __nv_bfloat16* qH = (__nv_bfloat16*)dsm;
    __nv_bfloat16* qL = (__nv_bfloat16*)(dsm + T64);
    __nv_bfloat16* kH = (__nv_bfloat16*)(dsm + 2 * T64);
    __nv_bfloat16* kL = (__nv_bfloat16*)(dsm + 3 * T64);
    int t = threadIdx.x, w = t >> 5, lane = t & 31;
    int wm = (w & 1) * 64, wn = (w >> 1) * 32;
    int g = lane >> 2, tg = lane & 3;
    float acc[4][4][4] = {};
    int bx = blockIdx.x, by = blockIdx.y, bh = blockIdx.z;
    size_t qo = ((size_t)bh * SS + by * 128) * HD;
    size_t ko = ((size_t)bh * SS + bx * 128) * HD;
    stage_cp64(qH, g_qhi + qo, HD, t);
    stage_cp64(qL, g_qlo + qo, HD, t);
    stage_cp64(kH, g_khi + ko, HD, t);
    stage_cp64(kL, g_klo + ko, HD, t);
    CP_COMMIT();
    CP_WAIT0();
    __syncthreads();
    mma_chunk<SA2, 4, 3>(base, base + T64, base + 2 * T64, base + 3 * T64,
                         wm, wn, lane, acc);
    float* abase = attn + (size_t)bh * SS * SS;
#pragma unroll
    for (int mt = 0; mt < 4; mt++)
#pragma unroll
        for (int nt = 0; nt < 4; nt++) {
            float* c = acc[mt][nt];
#pragma unroll
            for (int half = 0; half < 2; half++) {
                int m = by * 128 + wm + mt * 16 + g + half * 8;
                int n = bx * 128 + wn + nt * 8 + tg * 2;
                float2 o;
                o.x = c[half * 2];
                o.y = c[half * 2 + 1];
                *(float2*)&abase[(size_t)m * SS + n] = o;
            }
        }
}

// ---------------- K8: masked softmax (exp cached in smem) ---------------------
__global__ __launch_bounds__(256) void softmax_kernel(float* __restrict__ attn) {
    extern __shared__ float smemf[];
    float* rows = smemf;
    unsigned char* mk = (unsigned char*)(rows + 8 * SS);
    int bh = blockIdx.y;
    int t = threadIdx.x, w = t >> 5, lane = t & 31;
    int i = blockIdx.x * 8 + w;
    for (int j = t; j < SS; j += 256) mk[j] = (unsigned char)g_mark[bh * SS + j];
    float* gp = attn + ((size_t)bh * SS + i) * SS;
    float* rb = rows + w * SS;
    for (int it = 0; it < 64; ++it) rb[lane + it * 32] = gp[lane + it * 32];
    __syncthreads();
    float m = -1e30f;
    for (int it = 0; it < 64; ++it) {
        int j = lane + it * 32;
        int rel = j - i;
        bool ms = (rel >= -W2 && rel <= W2) || mk[j];
        if (ms) m = fmaxf(m, rb[j]);
    }
#pragma unroll
    for (int off = 16; off; off >>= 1) m = fmaxf(m, __shfl_xor_sync(0xffffffffu, m, off));
    float sum = 0.f;
    for (int it = 0; it < 64; ++it) {
        int j = lane + it * 32;
        int rel = j - i;
        bool ms = (rel >= -W2 && rel <= W2) || mk[j];
        if (ms) {
            float e = __expf(rb[j] - m);
            rb[j] = e;
            sum += e;
        }
    }
#pragma unroll
    for (int off = 16; off; off >>= 1) sum += __shfl_xor_sync(0xffffffffu, sum, off);
    float inv = 1.0f / sum;
    for (int it = 0; it < 64; ++it) {
        int j = lane + it * 32;
        int rel = j - i;
        bool ms = (rel >= -W2 && rel <= W2) || mk[j];
        gp[j] = ms ? rb[j] * inv : 0.f;
    }
}

// ---------------- K9: AV GEMM (pipelined, ldmatrix, pass-outer) ---------------
__global__ __launch_bounds__(256, 2) void av_mma(const float* __restrict__ attn) {
    __shared__ __nv_bfloat16 sAh[128 * SA], sAl[128 * SA];
    __shared__ __nv_bfloat16 sVh[2][64 * SA], sVl[2][64 * SA];
    int t = threadIdx.x, w = t >> 5, lane = t & 31;
    int wm = (w & 1) * 64, wn = (w >> 1) * 16;
    int g = lane >> 2, tg = lane & 3;
    int quad = lane >> 3, within = lane & 7;
    int bx = blockIdx.x, bh = blockIdx.y;
    const float* Ap = attn + ((size_t)bh * SS + bx * 128) * SS;
    const __nv_bfloat16* Vh = g_vthi + (size_t)bh * HD * SS;
    const __nv_bfloat16* Vl = g_vtlo + (size_t)bh * HD * SS;
    uint32_t sAh_u = s2u(sAh), sAl_u = s2u(sAl);
    uint32_t sVh_u[2] = {s2u(sVh[0]), s2u(sVh[1])};
    uint32_t sVl_u[2] = {s2u(sVl[0]), s2u(sVl[1])};
    int arow = (wm + within + (quad & 1) * 8) * SA + (quad >> 1) * 8;
    int brow = (wn + within + (quad >> 1) * 8) * SA + (quad & 1) * 8;

    float2 pv[8];
#pragma unroll
    for (int i = 0; i < 8; i++) {
        int lin = t + i * 256;
        int r = lin >> 4, h = lin & 15;
        pv[i] = *(const float2*)&Ap[(size_t)r * SS + h * 2];
    }
#pragma unroll
    for (int i = 0; i < 2; i++) {
        int lin = t + i * 256;
        int r = lin >> 3, h = lin & 7;
        cp8(&sVh[0][r * SA + h * 4], &Vh[(size_t)r * SS + h * 4]);
        cp8(&sVl[0][r * SA + h * 4], &Vl[(size_t)r * SS + h * 4]);
    }
    CP_COMMIT();

    float acc[4][2][4] = {};
    for (int ch = 0; ch < SS / 32; ++ch) {
        int buf = ch & 1;
        __syncthreads();
#pragma unroll
        for (int i = 0; i < 8; i++) {
            int lin = t + i * 256;
            int r = lin >> 4, h = lin & 15;
            uint32_t hi, lo;
            split2(pv[i].x, pv[i].y, hi, lo);
            *(uint32_t*)&sAh[r * SA + h * 2] = hi;
            *(uint32_t*)&sAl[r * SA + h * 2] = lo;
        }
        if (ch + 1 < SS / 32) {
            int k0n = (ch + 1) * 32;
#pragma unroll
            for (int i = 0; i < 2; i++) {
                int lin = t + i * 256;
                int r = lin >> 3, h = lin & 7;
                cp8(&sVh[buf ^ 1][r * SA + h * 4], &Vh[(size_t)r * SS + k0n + h * 4]);
                cp8(&sVl[buf ^ 1][r * SA + h * 4], &Vl[(size_t)r * SS + k0n + h * 4]);
            }
            CP_COMMIT();
#pragma unroll
            for (int i = 0; i < 8; i++) {
                int lin = t + i * 256;
                int r = lin >> 4, h = lin & 15;
                pv[i] = *(const float2*)&Ap[(size_t)r * SS + k0n + h * 2];
            }
            CP_WAIT1();
        } else {
            CP_WAIT0();
        }
        __syncthreads();
#pragma unroll
        for (int s = 0; s < 2; s++) {
            int kk = s * 16;
            uint32_t ah[4][4], al[4][4], bhf[4], blf[4];
#pragma unroll
            for (int mt = 0; mt < 4; mt++) {
                uint32_t off = (uint32_t)(arow + mt * 16 * SA + kk) * 2;
                ldsm_x4(ah[mt], sAh_u + off);
                ldsm_x4(al[mt], sAl_u + off);
            }
            {
                uint32_t off = (uint32_t)(brow + kk) * 2;
                ldsm_x4(bhf, sVh_u[buf] + off);
                ldsm_x4(blf, sVl_u[buf] + off);
            }
            // pass-outer: hh (all 8), hl (all 8), lh (all 8)
#pragma unroll
            for (int p = 0; p < 3; p++) {
                const uint32_t (*ap)[4] = (p == 2) ? al : ah;
#pragma unroll
                for (int nt = 0; nt < 2; nt++) {
                    const uint32_t* bp = (p == 1) ? &blf[nt * 2] : &bhf[nt * 2];
#pragma unroll
                    for (int mt = 0; mt < 4; mt++)
                        mma16816(acc[mt][nt], ap[mt], bp);
                }
            }
        }
    }
    int b = bh >> 4, h = bh & 15;
#pragma unroll
    for (int mt = 0; mt < 4; mt++)
#pragma unroll
        for (int nt = 0; nt < 2; nt++) {
            float* c = acc[mt][nt];
#pragma unroll
            for (int half = 0; half < 2; half++) {
                int s = bx * 128 + wm + mt * 16 + g + half * 8;
                int d = wn + nt * 8 + tg * 2;
                size_t di = ((size_t)(b * SS + s)) * DD + h * 64 + d;
                uint32_t hi, lo;
                split2(c[half * 2], c[half * 2 + 1], hi, lo);
                *(uint32_t*)&g_ohi[di] = hi;
                *(uint32_t*)&g_olo[di] = lo;
            }
        }
}

// ---------------- K10: output projection --------------------------------------
__global__ __launch_bounds__(256, 2) void proj_mma(const float* __restrict__ bias,
                                                   float* __restrict__ out) {
    GEMM_PROLOG();
    int bx = blockIdx.x, by = blockIdx.y;
    gemm_db(g_ohi + (size_t)by * 128 * DD, g_olo + (size_t)by * 128 * DD, DD,
            g_w1hi + (size_t)bx * 128 * DD, g_w1lo + (size_t)bx * 128 * DD, DD,
            DD, dsm, t, wm, wn, lane, acc);
#pragma unroll
    for (int mt = 0; mt < 4; mt++)
#pragma unroll
        for (int nt = 0; nt < 4; nt++) {
            float* c = acc[mt][nt];
#pragma unroll
            for (int half = 0; half < 2; half++) {
                int m = by * 128 + wm + mt * 16 + g + half * 8;
                int n = bx * 128 + wn + nt * 8 + tg * 2;
                float2 o;
                o.x = c[half * 2] + bias[n];
                o.y = c[half * 2 + 1] + bias[n + 1];
                *(float2*)&out[(size_t)m * DD + n] = o;
            }
        }
}

// ---------------- launch ------------------------------------------------------
extern "C" void kernel_launch(void* const* d_in, const int* in_sizes, int n_in,
                              void* d_out, int out_size) {
    const float* x = (const float*)d_in[0];
    const float* qkv_w = (const float*)d_in[1];
    const float* qkv_b = (const float*)d_in[2];
    const float* out_w = (const float*)d_in[3];
    const float* out_b = (const float*)d_in[4];
    float* out = (float*)d_out;
    float* attn = out + (size_t)BB * SS * DD;

    const int SM_SMEM = 8 * SS * 4 + SS;
    cudaFuncSetAttribute(softmax_kernel, cudaFuncAttributeMaxDynamicSharedMemorySize, SM_SMEM);
    cudaFuncSetAttribute(qkv_mma, cudaFuncAttributeMaxDynamicSharedMemorySize, GEMM_DSMEM);
    cudaFuncSetAttribute(score_mma, cudaFuncAttributeMaxDynamicSharedMemorySize, SCORE_SMEM);
    cudaFuncSetAttribute(proj_mma, cudaFuncAttributeMaxDynamicSharedMemorySize, GEMM_DSMEM);
    cudaFuncSetAttribute(distkth_mma, cudaFuncAttributeMaxDynamicSharedMemorySize, DIST_SMEM);

    cvt_x<<<(BB * SS * DD + 255) / 256, 256>>>(x);
    cvt_w3<<<(3 * DD * DD + 255) / 256, 256>>>(qkv_w);
    cvt_w1<<<(DD * DD + 255) / 256, 256>>>(out_w);

    qkv_mma<<<dim3(24, 32), 256, GEMM_DSMEM>>>(qkv_b);
    stats_kernel<<<BH, 256>>>(x);
    distkth_mma<<<dim3(16, BH), 256, DIST_SMEM>>>();
    tls_kernel<<<BH, 256>>>();
    sort_mark_kernel<<<BH, 1024>>>();
    score_mma<<<dim3(16, 16, BH), 256, SCORE_SMEM>>>(attn);
    softmax_kernel<<<dim3(SS / 8, BH), 256, SM_SMEM>>>(attn);
    av_mma<<<dim3(16, BH), 256>>>(attn);
    proj_mma<<<dim3(8, 32), 256, GEMM_DSMEM>>>(out_b, out);
}

// round 11
// speedup vs baseline: 1.2019x; 1.2019x over previous
#include <cuda_runtime.h>
#include <cuda_bf16.h>
#include <math.h>
#include <stdint.h>

#define BB 2
#define SS 2048
#define DD 1024
#define HH 16
#define HD 64
#define BH (BB*HH)
#define NKEEP 675
#define W2 64
#define SA 40   // smem row stride (bf16), 32-wide K chunks
#define SA2 72  // smem row stride (bf16), 64-wide K chunks

// ---------------- scratch -----------------------------------------------------
__device__ float g_sq[BH*SS];
__device__ float g_d2c[BH*SS];
__device__ float g_d2cmax[BH];
__device__ float g_kd[BH*SS];
__device__ float g_kdmax[BH];
__device__ float g_tls[BH*SS];
__device__ int   g_mark[BH*SS];

__device__ __align__(256) __nv_bfloat16 g_xhi[BB*SS*DD];
__device__ __align__(256) __nv_bfloat16 g_xlo[BB*SS*DD];
__device__ __align__(256) __nv_bfloat16 g_w3hi[3*DD*DD];
__device__ __align__(256) __nv_bfloat16 g_w3lo[3*DD*DD];
__device__ __align__(256) __nv_bfloat16 g_w1hi[DD*DD];
__device__ __align__(256) __nv_bfloat16 g_w1lo[DD*DD];
__device__ __align__(256) __nv_bfloat16 g_qhi[BH*SS*HD];
__device__ __align__(256) __nv_bfloat16 g_qlo[BH*SS*HD];
__device__ __align__(256) __nv_bfloat16 g_khi[BH*SS*HD];
__device__ __align__(256) __nv_bfloat16 g_klo[BH*SS*HD];
__device__ __align__(256) __nv_bfloat16 g_vthi[BH*HD*SS];  // V^T: [bh][d][s]
__device__ __align__(256) __nv_bfloat16 g_vtlo[BH*HD*SS];
__device__ __align__(256) __nv_bfloat16 g_ohi[BB*SS*DD];
__device__ __align__(256) __nv_bfloat16 g_olo[BB*SS*DD];

// ---------------- helpers -----------------------------------------------------
__device__ __forceinline__ uint32_t s2u(const void* p) {
    uint32_t a;
    asm("{ .reg .u64 t; cvta.to.shared.u64 t, %1; cvt.u32.u64 %0, t; }" : "=r"(a) : "l"(p));
    return a;
}
__device__ __forceinline__ void mma16816(float* c, const uint32_t* a, const uint32_t* b) {
    asm volatile(
        "mma.sync.aligned.m16n8k16.row.col.f32.bf16.bf16.f32 "
        "{%0,%1,%2,%3}, {%4,%5,%6,%7}, {%8,%9}, {%0,%1,%2,%3};"
        : "+f"(c[0]), "+f"(c[1]), "+f"(c[2]), "+f"(c[3])
        : "r"(a[0]), "r"(a[1]), "r"(a[2]), "r"(a[3]), "r"(b[0]), "r"(b[1]));
}
__device__ __forceinline__ void ldsm_x4(uint32_t* r, uint32_t addr) {
    asm volatile("ldmatrix.sync.aligned.m8n8.x4.shared.b16 {%0,%1,%2,%3}, [%4];"
                 : "=r"(r[0]), "=r"(r[1]), "=r"(r[2]), "=r"(r[3]) : "r"(addr));
}
__device__ __forceinline__ void split2(float x, float y, uint32_t& hi, uint32_t& lo) {
    __nv_bfloat16 hx = __float2bfloat16(x), hy = __float2bfloat16(y);
    __nv_bfloat162 h, l;
    h.x = hx; h.y = hy;
    l.x = __float2bfloat16(x - __bfloat162float(hx));
    l.y = __float2bfloat16(y - __bfloat162float(hy));
    hi = *(uint32_t*)&h;
    lo = *(uint32_t*)&l;
}
__device__ __forceinline__ void cp8(__nv_bfloat16* dst, const __nv_bfloat16* src) {
    uint32_t d = s2u(dst);
    asm volatile("cp.async.ca.shared.global [%0], [%1], 8;" :: "r"(d), "l"(src) : "memory");
}
#define CP_COMMIT() asm volatile("cp.async.commit_group;" ::: "memory")
#define CP_WAIT1() asm volatile("cp.async.wait_group 1;" ::: "memory")
#define CP_WAIT0() asm volatile("cp.async.wait_group 0;" ::: "memory")

// cp.async stage of a [128 x 32] bf16 tile -> smem [128][SA]
__device__ __forceinline__ void stage_cp(__nv_bfloat16* dst, const __nv_bfloat16* src,
                                         int ld, int k0, int t) {
#pragma unroll
    for (int i = 0; i < 4; i++) {
        int lin = t + i * 256;
        int r = lin >> 3, h = lin & 7;
        cp8(&dst[r * SA + h * 4], &src[(size_t)r * ld + k0 + h * 4]);
    }
}
// cp.async stage of a [128 x 64] bf16 tile -> smem [128][SA2]
__device__ __forceinline__ void stage_cp64(__nv_bfloat16* dst, const __nv_bfloat16* src,
                                           int ld, int t) {
#pragma unroll
    for (int i = 0; i < 8; i++) {
        int lin = t + i * 256;
        int r = lin >> 4, h = lin & 15;
        cp8(&dst[r * SA2 + h * 4], &src[(size_t)r * ld + h * 4]);
    }
}

// ---- fused-pass MMA over one K chunk via ldmatrix, pass-outer issue order ----
template<int STR, int NSTEP, int NPASS>
__device__ __forceinline__ void mma_chunk(uint32_t Ah, uint32_t Al,
                                          uint32_t Bh, uint32_t Bl,
                                          int wm, int wn, int lane, float (*acc)[4][4]) {
    int quad = lane >> 3, within = lane & 7;
    int arow = (wm + within + (quad & 1) * 8) * STR + (quad >> 1) * 8;
    int brow = (wn + within + (quad >> 1) * 8) * STR + (quad & 1) * 8;
#pragma unroll
    for (int s = 0; s < NSTEP; s++) {
        int kk = s * 16;
        uint32_t ah[4][4], al[4][4], bh[2][4], bl[2][4];
#pragma unroll
        for (int mt = 0; mt < 4; mt++) {
            uint32_t off = (uint32_t)(arow + mt * 16 * STR + kk) * 2;
            ldsm_x4(ah[mt], Ah + off);
            ldsm_x4(al[mt], Al + off);
        }
#pragma unroll
        for (int np = 0; np < 2; np++) {
            uint32_t off = (uint32_t)(brow + np * 16 * STR + kk) * 2;
            ldsm_x4(bh[np], Bh + off);
            ldsm_x4(bl[np], Bl + off);
        }
#pragma unroll
        for (int p = 0; p < NPASS; p++) {
            const uint32_t (*ap)[4] = (p >= 2) ? al : ah;
#pragma unroll
            for (int nt = 0; nt < 4; nt++) {
                const uint32_t* bp = (p & 1) ? &bl[nt >> 1][(nt & 1) * 2]
                                             : &bh[nt >> 1][(nt & 1) * 2];
#pragma unroll
                for (int mt = 0; mt < 4; mt++)
                    mma16816(acc[mt][nt], ap[mt], bp);
            }
        }
    }
}

// double-buffered mainloop for K>=128 GEMMs (tiles: 0=Ahi 1=Alo 2=Bhi 3=Blo)
#define TILE_BYTES (128 * SA * 2)
__device__ __forceinline__ void gemm_db(const __nv_bfloat16* Ahi, const __nv_bfloat16* Alo, int lda,
                                        const __nv_bfloat16* Bhi, const __nv_bfloat16* Blo, int ldb,
                                        int K, char* dsm, int t, int wm, int wn,
                                        int lane, float (*acc)[4][4]) {
    uint32_t base = s2u(dsm);
    auto tile = [&](int buf, int idx) {
        return (__nv_bfloat16*)(dsm + (buf * 4 + idx) * TILE_BYTES);
    };
    stage_cp(tile(0, 0), Ahi, lda, 0, t);
    stage_cp(tile(0, 1), Alo, lda, 0, t);
    stage_cp(tile(0, 2), Bhi, ldb, 0, t);
    stage_cp(tile(0, 3), Blo, ldb, 0, t);
    CP_COMMIT();
    int nch = K / 32;
    for (int ch = 0; ch < nch; ++ch) {
        int buf = ch & 1;
        if (ch + 1 < nch) {
            int nb = buf ^ 1, k0 = (ch + 1) * 32;
            stage_cp(tile(nb, 0), Ahi, lda, k0, t);
            stage_cp(tile(nb, 1), Alo, lda, k0, t);
            stage_cp(tile(nb, 2), Bhi, ldb, k0, t);
            stage_cp(tile(nb, 3), Blo, ldb, k0, t);
            CP_COMMIT();
            CP_WAIT1();
        } else {
            CP_WAIT0();
        }
        __syncthreads();
        uint32_t tb = base + buf * 4 * TILE_BYTES;
        mma_chunk<SA, 2, 3>(tb, tb + TILE_BYTES, tb + 2 * TILE_BYTES, tb + 3 * TILE_BYTES,
                            wm, wn, lane, acc);
        __syncthreads();
    }
}
#define GEMM_DSMEM (8 * TILE_BYTES)

#define GEMM_PROLOG() \
    extern __shared__ char dsm[]; \
    int t = threadIdx.x, w = t >> 5, lane = t & 31; \
    int wm = (w & 1) * 64, wn = (w >> 1) * 32; \
    int g = lane >> 2, tg = lane & 3; \
    float acc[4][4][4] = {};

// ---------------- cvt: fp32 -> (hi, lo) bf16 ----------------------------------
__global__ __launch_bounds__(256) void cvt_x(const float* __restrict__ s) {
    int i = blockIdx.x * 256 + threadIdx.x;
    if (i < BB * SS * DD) {
        float v = s[i];
        __nv_bfloat16 h = __float2bfloat16(v);
        g_xhi[i] = h;
        g_xlo[i] = __float2bfloat16(v - __bfloat162float(h));
    }
}
__global__ __launch_bounds__(256) void cvt_w3(const float* __restrict__ s) {
    int i = blockIdx.x * 256 + threadIdx.x;
    if (i < 3 * DD * DD) {
        float v = s[i];
        __nv_bfloat16 h = __float2bfloat16(v);
        g_w3hi[i] = h;
        g_w3lo[i] = __float2bfloat16(v - __bfloat162float(h));
    }
}
__global__ __launch_bounds__(256) void cvt_w1(const float* __restrict__ s) {
    int i = blockIdx.x * 256 + threadIdx.x;
    if (i < DD * DD) {
        float v = s[i];
        __nv_bfloat16 h = __float2bfloat16(v);
        g_w1hi[i] = h;
        g_w1lo[i] = __float2bfloat16(v - __bfloat162float(h));
    }
}

// ---------------- K1: QKV GEMM ------------------------------------------------
__global__ __launch_bounds__(256, 2) void qkv_mma(const float* __restrict__ bias) {
    GEMM_PROLOG();
    int bx = blockIdx.x, by = blockIdx.y;
    gemm_db(g_xhi + (size_t)by * 128 * DD, g_xlo + (size_t)by * 128 * DD, DD,
            g_w3hi + (size_t)bx * 128 * DD, g_w3lo + (size_t)bx * 128 * DD, DD,
            DD, dsm, t, wm, wn, lane, acc);
#pragma unroll
    for (int mt = 0; mt < 4; mt++)
#pragma unroll
        for (int nt = 0; nt < 4; nt++) {
            float* c = acc[mt][nt];
#pragma unroll
            for (int half = 0; half < 2; half++) {
                int m = by * 128 + wm + mt * 16 + g + half * 8;
                int n = bx * 128 + wn + nt * 8 + tg * 2;
                float v0 = c[half * 2] + bias[n];
                float v1 = c[half * 2 + 1] + bias[n + 1];
                int which = n >> 10, h = (n >> 6) & 15, d = n & 63;
                int b = m >> 11, s = m & (SS - 1);
                int bh = b * HH + h;
                if (which == 0) {
                    size_t di = ((size_t)bh * SS + s) * HD + d;
                    uint32_t hi, lo;
                    split2(v0 * 0.125f, v1 * 0.125f, hi, lo);
                    *(uint32_t*)&g_qhi[di] = hi;
                    *(uint32_t*)&g_qlo[di] = lo;
                } else if (which == 1) {
                    size_t di = ((size_t)bh * SS + s) * HD + d;
                    uint32_t hi, lo;
                    split2(v0, v1, hi, lo);
                    *(uint32_t*)&g_khi[di] = hi;
                    *(uint32_t*)&g_klo[di] = lo;
                } else {
                    size_t di = ((size_t)bh * HD + d) * SS + s;
                    __nv_bfloat16 h0 = __float2bfloat16(v0), h1 = __float2bfloat16(v1);
                    g_vthi[di] = h0;
                    g_vtlo[di] = __float2bfloat16(v0 - __bfloat162float(h0));
                    g_vthi[di + SS] = h1;
                    g_vtlo[di + SS] = __float2bfloat16(v1 - __bfloat162float(h1));
                }
            }
        }
}

// ---------------- K2: stats ---------------------------------------------------
__global__ __launch_bounds__(256) void stats_kernel(const float* __restrict__ x) {
    int bh = blockIdx.x;
    int b = bh / HH, h = bh % HH;
    int t = threadIdx.x;
    __shared__ float part[256];
    __shared__ float cent[64];
    int d = t & 63, grp = t >> 6;
    float acc = 0.f;
    for (int s = grp; s < SS; s += 4)
        acc += x[((size_t)(b * SS + s)) * DD + h * HD + d];
    part[t] = acc;
    __syncthreads();
    if (t < 64) cent[t] = (part[t] + part[t + 64] + part[t + 128] + part[t + 192]) * (1.0f / SS);
    __syncthreads();
    float lmax = 0.f;
    for (int s = t; s < SS; s += 256) {
        const float* xp = x + (size_t)(b * SS + s) * DD + h * HD;
        float sq = 0.f, dc2 = 0.f;
#pragma unroll
        for (int dd = 0; dd < HD; ++dd) {
            float v = xp[dd];
            sq += v * v;
            float wv = v - cent[dd];
            dc2 += wv * wv;
        }
        g_sq[bh * SS + s] = sq;
        float dc = sqrtf(dc2);
        g_d2c[bh * SS + s] = dc;
        lmax = fmaxf(lmax, dc);
    }
    __syncthreads();
    part[t] = lmax;
    __syncthreads();
    for (int off = 128; off > 0; off >>= 1) {
        if (t < off) part[t] = fmaxf(part[t], part[t + off]);
        __syncthreads();
    }
    if (t == 0) {
        g_d2cmax[bh] = part[0];
        g_kdmax[bh] = 0.f;
    }
}

// ---------------- K3+K4 fused: pairwise dist + 10th-smallest (occ 2) ----------
#define T64 (128 * SA2 * 2)
#define DK_SD (4 * T64)
#define DIST_SMEM (DK_SD + 128 * 66 * 4)
__global__ __launch_bounds__(256, 2) void distkth_mma() {
    extern __shared__ char dsm[];
    uint32_t base = s2u(dsm);
    __nv_bfloat16* aH = (__nv_bfloat16*)dsm;
    __nv_bfloat16* aL = (__nv_bfloat16*)(dsm + T64);
    __nv_bfloat16* bH = (__nv_bfloat16*)(dsm + 2 * T64);
    __nv_bfloat16* bL = (__nv_bfloat16*)(dsm + 3 * T64);
    float* sD = (float*)(dsm + DK_SD);
    int t = threadIdx.x, w = t >> 5, lane = t & 31;
    int wm = (w & 1) * 64, wn = (w >> 1) * 32;
    int g = lane >> 2, tg = lane & 3;
    int wphase = w >> 2;
    int bh = blockIdx.y;
    int m0 = blockIdx.x * 128;
    const __nv_bfloat16* xh = g_xhi + (size_t)(bh >> 4) * SS * DD + (bh & 15) * HD;
    const __nv_bfloat16* xl = g_xlo + (size_t)(bh >> 4) * SS * DD + (bh & 15) * HD;

#pragma unroll
    for (int i = 0; i < 8; i++) {
        int lin = t + i * 256;
        int r = lin >> 4, hh = lin & 15;
        *(uint2*)&aH[r * SA2 + hh * 4] = *(const uint2*)&xh[(size_t)(m0 + r) * DD + hh * 4];
        *(uint2*)&aL[r * SA2 + hh * 4] = *(const uint2*)&xl[(size_t)(m0 + r) * DD + hh * 4];
    }

    float ls[10];
#pragma unroll
    for (int q = 0; q < 10; q++) ls[q] = 1e30f;
    int row_l = t >> 1;
    int hhalf = t & 1;

    for (int ct = 0; ct < 16; ++ct) {
        stage_cp64(bH, xh + (size_t)ct * 128 * DD, DD, t);
        stage_cp64(bL, xl + (size_t)ct * 128 * DD, DD, t);
        CP_COMMIT();
        CP_WAIT0();
        __syncthreads();
        float acc[4][4][4];
#pragma unroll
        for (int a = 0; a < 4; a++)
#pragma unroll
            for (int b2 = 0; b2 < 4; b2++)
#pragma unroll
                for (int c2 = 0; c2 < 4; c2++) acc[a][b2][c2] = 0.f;
        mma_chunk<SA2, 4, 4>(base, base + T64, base + 2 * T64, base + 3 * T64,
                             wm, wn, lane, acc);
#pragma unroll
        for (int p = 0; p < 2; p++) {
            if (wphase == p) {
#pragma unroll
                for (int mt = 0; mt < 4; mt++)
#pragma unroll
                    for (int nt = 0; nt < 4; nt++) {
                        float* c = acc[mt][nt];
#pragma unroll
                        for (int half = 0; half < 2; half++) {
                            int ml = wm + mt * 16 + g + half * 8;
                            int nl = wn + nt * 8 + tg * 2;
                            float2 sqj = *(const float2*)&g_sq[bh * SS + ct * 128 + nl];
                            sD[ml * 66 + (nl - p * 64)] = sqj.x - 2.f * c[half * 2];
                            sD[ml * 66 + (nl - p * 64) + 1] = sqj.y - 2.f * c[half * 2 + 1];
                        }
                    }
            }
            __syncthreads();
            const float* rp = &sD[row_l * 66 + hhalf * 32];
#pragma unroll 8
            for (int i = 0; i < 32; ++i) {
                float v = rp[i];
                if (v < ls[9]) {
                    ls[9] = v;
#pragma unroll
                    for (int q = 9; q > 0; --q) {
                        if (ls[q] < ls[q - 1]) { float tm = ls[q]; ls[q] = ls[q - 1]; ls[q - 1] = tm; }
                    }
                }
            }
            __syncthreads();
        }
    }
#pragma unroll
    for (int q = 0; q < 10; q++) sD[row_l * 66 + hhalf * 10 + q] = ls[q];
    __syncthreads();
    if (hhalf == 0) {
        const float* a = &sD[row_l * 66];
        const float* b = a + 10;
        int ia = 0, ib = 0;
        float kth = 0.f;
#pragma unroll
        for (int it = 0; it < 10; ++it)
            kth = (a[ia] <= b[ib]) ? a[ia++] : b[ib++];
        int m = m0 + row_l;
        float kd = sqrtf(fmaxf(g_sq[bh * SS + m] + kth, 0.f));
        g_kd[bh * SS + m] = kd;
        atomicMax((int*)&g_kdmax[bh], __float_as_int(kd));
    }
}

// ---------------- K5: tls -----------------------------------------------------
__global__ __launch_bounds__(256) void tls_kernel() {
    int bh = blockIdx.x;
    int t = threadIdx.x;
    float dinv = 1.0f / (g_d2cmax[bh] + 1e-8f);
    float kinv = 1.0f / (g_kdmax[bh] + 1e-8f);
    for (int s = t; s < SS; s += 256) {
        float life = g_d2c[bh * SS + s] * dinv;
        float mmd = g_kd[bh * SS + s] * kinv;
        g_tls[bh * SS + s] = 0.7f * life + 0.3f * mmd;
    }
}

// ---------------- K6: bitonic sort + mark -------------------------------------
__global__ __launch_bounds__(1024) void sort_mark_kernel() {
    __shared__ float a[SS];
    int t = threadIdx.x;
    int bh = blockIdx.x;
    a[t] = g_tls[bh * SS + t];
    a[t + 1024] = g_tls[bh * SS + t + 1024];
    __syncthreads();
    for (int k = 2; k <= SS; k <<= 1) {
        for (int j = k >> 1; j > 0; j >>= 1) {
#pragma unroll
            for (int half = 0; half < 2; ++half) {
                int i = t + half * 1024;
                int ixj = i ^ j;
                if (ixj > i) {
                    bool up = ((i & k) == 0);
                    float xi = a[i], xj = a[ixj];
                    if (up ? (xi > xj) : (xi < xj)) { a[i] = xj; a[ixj] = xi; }
                }
            }
            __syncthreads();
        }
    }
    float thresh = a[SS - NKEEP];
    __syncthreads();
#pragma unroll
    for (int half = 0; half < 2; ++half) {
        int s = t + half * 1024;
        g_mark[bh * SS + s] = (g_tls[bh * SS + s] >= thresh) ? 1 : 0;
    }
}

// ---------------- K7: FUSED score + softmax + AV ------------------------------
// smem layout:
//   sweep1: qH@0 qL@18432 kH@36864 kL@55296           (73728 B)
//   sweep2 overlay: pH@0 pL@10240 sVh0@20480 sVl0@25600 sVh1@30720 sVl1@35840
//   stats @73728: m_f[128] inv[128] stats_m[128*4] stats_s[128*4] mk[2048]
#define AF_QH 0
#define AF_QL 18432
#define AF_KH 36864
#define AF_KL 55296
#define AF_PH 0
#define AF_PL 10240
#define AF_V0H 20480
#define AF_V0L 25600
#define AF_V1H 30720
#define AF_V1L 35840
#define AF_STAT 73728
#define AF_SMEM (73728 + 512 + 512 + 2048 + 2048 + 2048)
__global__ __launch_bounds__(256, 2) void attn_fused(float* __restrict__ attn) {
    extern __shared__ char dsm[];
    uint32_t base = s2u(dsm);
    int t = threadIdx.x, w = t >> 5, lane = t & 31;
    int wm = (w & 1) * 64, wn = (w >> 1) * 32;
    int g = lane >> 2, tg = lane & 3;
    int quad = lane >> 3, within = lane & 7;
    int bh = blockIdx.y;
    int m0 = blockIdx.x * 128;

    float* sm_f = (float*)(dsm + AF_STAT);
    float* s_inv = sm_f + 128;
    float* stats_m = s_inv + 128;   // [128][4]
    float* stats_s = stats_m + 512;
    unsigned char* mkS = (unsigned char*)(stats_s + 512);

    for (int j = t; j < SS; j += 256) mkS[j] = (unsigned char)g_mark[bh * SS + j];

    // stage Q once
    stage_cp64((__nv_bfloat16*)(dsm + AF_QH), g_qhi + ((size_t)bh * SS + m0) * HD, HD, t);
    stage_cp64((__nv_bfloat16*)(dsm + AF_QL), g_qlo + ((size_t)bh * SS + m0) * HD, HD, t);
    CP_COMMIT();

    float m_run[4][2], s_run[4][2];
#pragma unroll
    for (int a = 0; a < 4; a++)
#pragma unroll
        for (int b2 = 0; b2 < 2; b2++) { m_run[a][b2] = -1e30f; s_run[a][b2] = 0.f; }

    float* abase = attn + (size_t)bh * SS * SS;

    // ---- sweep 1: score MMA per tile, write raw s dense, online (m, sum) ----
    for (int ct = 0; ct < 16; ++ct) {
        __syncthreads();  // K buffer free (prev mma + epilogue done)
        stage_cp64((__nv_bfloat16*)(dsm + AF_KH), g_khi + ((size_t)bh * SS + ct * 128) * HD, HD, t);
        stage_cp64((__nv_bfloat16*)(dsm + AF_KL), g_klo + ((size_t)bh * SS + ct * 128) * HD, HD, t);
        CP_COMMIT();
        CP_WAIT0();
        __syncthreads();
        float acc[4][4][4];
#pragma unroll
        for (int a = 0; a < 4; a++)
#pragma unroll
            for (int b2 = 0; b2 < 4; b2++)
#pragma unroll
                for (int c2 = 0; c2 < 4; c2++) acc[a][b2][c2] = 0.f;
        mma_chunk<SA2, 4, 3>(base + AF_QH, base + AF_QL, base + AF_KH, base + AF_KL,
                             wm, wn, lane, acc);
        // write raw s + online stats
#pragma unroll
        for (int mt = 0; mt < 4; mt++)
#pragma unroll
            for (int half = 0; half < 2; half++) {
                int i = m0 + wm + mt * 16 + g + half * 8;
                float vals[8];
                bool msk[8];
                float tm = -1e30f;
#pragma unroll
                for (int nt = 0; nt < 4; nt++) {
                    int n = ct * 128 + wn + nt * 8 + tg * 2;
                    float2 o;
                    o.x = acc[mt][nt][half * 2];
                    o.y = acc[mt][nt][half * 2 + 1];
                    *(float2*)&abase[(size_t)i * SS + n] = o;
#pragma unroll
                    for (int e = 0; e < 2; e++) {
                        int j = n + e;
                        int rel = j - i;
                        bool ms = (rel >= -W2 && rel <= W2) || mkS[j];
                        vals[nt * 2 + e] = acc[mt][nt][half * 2 + e];
                        msk[nt * 2 + e] = ms;
                        if (ms) tm = fmaxf(tm, vals[nt * 2 + e]);
                    }
                }
                tm = fmaxf(tm, __shfl_xor_sync(0xffffffffu, tm, 1));
                tm = fmaxf(tm, __shfl_xor_sync(0xffffffffu, tm, 2));
                float newm = fmaxf(m_run[mt][half], tm);
                float add = 0.f;
#pragma unroll
                for (int q = 0; q < 8; q++)
                    if (msk[q]) add += __expf(vals[q] - newm);
                add += __shfl_xor_sync(0xffffffffu, add, 1);
                add += __shfl_xor_sync(0xffffffffu, add, 2);
                s_run[mt][half] = s_run[mt][half] * __expf(m_run[mt][half] - newm) + add;
                m_run[mt][half] = newm;
            }
    }
    __syncthreads();
    // combine per-warp stats
    if (tg == 0) {
#pragma unroll
        for (int mt = 0; mt < 4; mt++)
#pragma unroll
            for (int half = 0; half < 2; half++) {
                int r = wm + mt * 16 + g + half * 8;
                stats_m[r * 4 + (w >> 1)] = m_run[mt][half];
                stats_s[r * 4 + (w >> 1)] = s_run[mt][half];
            }
    }
    __syncthreads();
    if (t < 128) {
        float mf = stats_m[t * 4];
        mf = fmaxf(mf, stats_m[t * 4 + 1]);
        mf = fmaxf(mf, stats_m[t * 4 + 2]);
        mf = fmaxf(mf, stats_m[t * 4 + 3]);
        float sf = 0.f;
#pragma unroll
        for (int c = 0; c < 4; c++)
            sf += stats_s[t * 4 + c] * __expf(stats_m[t * 4 + c] - mf);
        sm_f[t] = mf;
        s_inv[t] = 1.0f / sf;
    }
    __syncthreads();

    // ---- sweep 2: read raw s, write p, split to P smem, AV MMA ----
    int wn2 = (w >> 1) * 16;
    __nv_bfloat16* sPh = (__nv_bfloat16*)(dsm + AF_PH);
    __nv_bfloat16* sPl = (__nv_bfloat16*)(dsm + AF_PL);
    __nv_bfloat16* sVhp[2] = {(__nv_bfloat16*)(dsm + AF_V0H), (__nv_bfloat16*)(dsm + AF_V1H)};
    __nv_bfloat16* sVlp[2] = {(__nv_bfloat16*)(dsm + AF_V0L), (__nv_bfloat16*)(dsm + AF_V1L)};
    uint32_t sPh_u = base + AF_PH, sPl_u = base + AF_PL;
    uint32_t sVh_u[2] = {base + AF_V0H, base + AF_V1H};
    uint32_t sVl_u[2] = {base + AF_V0L, base + AF_V1L};
    const __nv_bfloat16* Vh = g_vthi + (size_t)bh * HD * SS;
    const __nv_bfloat16* Vl = g_vtlo + (size_t)bh * HD * SS;
    const float* Ap = abase + (size_t)m0 * SS;
    int arow = (wm + within + (quad & 1) * 8) * SA + (quad >> 1) * 8;
    int brow = (wn2 + within + (quad >> 1) * 8) * SA + (quad & 1) * 8;

    float2 pv[8];
#pragma unroll
    for (int i = 0; i < 8; i++) {
        int lin = t + i * 256;
        int r = lin >> 4, h = lin & 15;
        pv[i] = *(const float2*)&Ap[(size_t)r * SS + h * 2];
    }
#pragma unroll
    for (int i = 0; i < 2; i++) {
        int lin = t + i * 256;
        int r = lin >> 3, h = lin & 7;
        cp8(&sVhp[0][r * SA + h * 4], &Vh[(size_t)r * SS + h * 4]);
        cp8(&sVlp[0][r * SA + h * 4], &Vl[(size_t)r * SS + h * 4]);
    }
    CP_COMMIT();

    float acc2[4][2][4] = {};
    for (int ch = 0; ch < SS / 32; ++ch) {
        int buf = ch & 1;
        __syncthreads();
        // transform raw s -> p; write p to attn; split into P smem
#pragma unroll
        for (int i = 0; i < 8; i++) {
            int lin = t + i * 256;
            int r = lin >> 4, h = lin & 15;
            int ig = m0 + r;
            int j0 = ch * 32 + h * 2;
            float mf = sm_f[r], iv = s_inv[r];
            int rel0 = j0 - ig, rel1 = j0 + 1 - ig;
            bool ms0 = (rel0 >= -W2 && rel0 <= W2) || mkS[j0];
            bool ms1 = (rel1 >= -W2 && rel1 <= W2) || mkS[j0 + 1];
            float p0 = ms0 ? __expf(pv[i].x - mf) * iv : 0.f;
            float p1 = ms1 ? __expf(pv[i].y - mf) * iv : 0.f;
            float2 o; o.x = p0; o.y = p1;
            *(float2*)&abase[(size_t)ig * SS + j0] = o;
            uint32_t hi, lo;
            split2(p0, p1, hi, lo);
            *(uint32_t*)&sPh[r * SA + h * 2] = hi;
            *(uint32_t*)&sPl[r * SA + h * 2] = lo;
        }
        if (ch + 1 < SS / 32) {
            int k0n = (ch + 1) * 32;
#pragma unroll
            for (int i = 0; i < 2; i++) {
                int lin = t + i * 256;
                int r = lin >> 3, h = lin & 7;
                cp8(&sVhp[buf ^ 1][r * SA + h * 4], &Vh[(size_t)r * SS + k0n + h * 4]);
                cp8(&sVlp[buf ^ 1][r * SA + h * 4], &Vl[(size_t)r * SS + k0n + h * 4]);
            }
            CP_COMMIT();
#pragma unroll
            for (int i = 0; i < 8; i++) {
                int lin = t + i * 256;
                int r = lin >> 4, h = lin & 15;
                pv[i] = *(const float2*)&Ap[(size_t)r * SS + k0n + h * 2];
            }
            CP_WAIT1();
        } else {
            CP_WAIT0();
        }
        __syncthreads();
#pragma unroll
        for (int s = 0; s < 2; s++) {
            int kk = s * 16;
            uint32_t ah[4][4], al[4][4], bhf[4], blf[4];
#pragma unroll
            for (int mt = 0; mt < 4; mt++) {
                uint32_t off = (uint32_t)(arow + mt * 16 * SA + kk) * 2;
                ldsm_x4(ah[mt], sPh_u + off);
                ldsm_x4(al[mt], sPl_u + off);
            }
            {
                uint32_t off = (uint32_t)(brow + kk) * 2;
                ldsm_x4(bhf, sVh_u[buf] + off);
                ldsm_x4(blf, sVl_u[buf] + off);
            }
#pragma unroll
            for (int p = 0; p < 3; p++) {
                const uint32_t (*ap)[4] = (p == 2) ? al : ah;
#pragma unroll
                for (int nt = 0; nt < 2; nt++) {
                    const uint32_t* bp = (p == 1) ? &blf[nt * 2] : &bhf[nt * 2];
#pragma unroll
                    for (int mt = 0; mt < 4; mt++)
                        mma16816(acc2[mt][nt], ap[mt], bp);
                }
            }
        }
    }
    int b = bh >> 4, h = bh & 15;
#pragma unroll
    for (int mt = 0; mt < 4; mt++)
#pragma unroll
        for (int nt = 0; nt < 2; nt++) {
            float* c = acc2[mt][nt];
#pragma unroll
            for (int half = 0; half < 2; half++) {
                int s = m0 + wm + mt * 16 + g + half * 8;
                int d = wn2 + nt * 8 + tg * 2;
                size_t di = ((size_t)(b * SS + s)) * DD + h * 64 + d;
                uint32_t hi, lo;
                split2(c[half * 2], c[half * 2 + 1], hi, lo);
                *(uint32_t*)&g_ohi[di] = hi;
                *(uint32_t*)&g_olo[di] = lo;
            }
        }
}

// ---------------- K10: output projection --------------------------------------
__global__ __launch_bounds__(256, 2) void proj_mma(const float* __restrict__ bias,
                                                   float* __restrict__ out) {
    GEMM_PROLOG();
    int bx = blockIdx.x, by = blockIdx.y;
    gemm_db(g_ohi + (size_t)by * 128 * DD, g_olo + (size_t)by * 128 * DD, DD,
            g_w1hi + (size_t)bx * 128 * DD, g_w1lo + (size_t)bx * 128 * DD, DD,
            DD, dsm, t, wm, wn, lane, acc);
#pragma unroll
    for (int mt = 0; mt < 4; mt++)
#pragma unroll
        for (int nt = 0; nt < 4; nt++) {
            float* c = acc[mt][nt];
#pragma unroll
            for (int half = 0; half < 2; half++) {
                int m = by * 128 + wm + mt * 16 + g + half * 8;
                int n = bx * 128 + wn + nt * 8 + tg * 2;
                float2 o;
                o.x = c[half * 2] + bias[n];
                o.y = c[half * 2 + 1] + bias[n + 1];
                *(float2*)&out[(size_t)m * DD + n] = o;
            }
        }
}

// ---------------- launch ------------------------------------------------------
extern "C" void kernel_launch(void* const* d_in, const int* in_sizes, int n_in,
                              void* d_out, int out_size) {
    const float* x = (const float*)d_in[0];
    const float* qkv_w = (const float*)d_in[1];
    const float* qkv_b = (const float*)d_in[2];
    const float* out_w = (const float*)d_in[3];
    const float* out_b = (const float*)d_in[4];
    float* out = (float*)d_out;
    float* attn = out + (size_t)BB * SS * DD;

    cudaFuncSetAttribute(qkv_mma, cudaFuncAttributeMaxDynamicSharedMemorySize, GEMM_DSMEM);
    cudaFuncSetAttribute(proj_mma, cudaFuncAttributeMaxDynamicSharedMemorySize, GEMM_DSMEM);
    cudaFuncSetAttribute(distkth_mma, cudaFuncAttributeMaxDynamicSharedMemorySize, DIST_SMEM);
    cudaFuncSetAttribute(attn_fused, cudaFuncAttributeMaxDynamicSharedMemorySize, AF_SMEM);

    cvt_x<<<(BB * SS * DD + 255) / 256, 256>>>(x);
    cvt_w3<<<(3 * DD * DD + 255) / 256, 256>>>(qkv_w);
    cvt_w1<<<(DD * DD + 255) / 256, 256>>>(out_w);

    qkv_mma<<<dim3(24, 32), 256, GEMM_DSMEM>>>(qkv_b);
    stats_kernel<<<BH, 256>>>(x);
    distkth_mma<<<dim3(16, BH), 256, DIST_SMEM>>>();
    tls_kernel<<<BH, 256>>>();
    sort_mark_kernel<<<BH, 1024>>>();
    attn_fused<<<dim3(16, BH), 256, AF_SMEM>>>(attn);
    proj_mma<<<dim3(8, 32), 256, GEMM_DSMEM>>>(out_b, out);
}